// round 1
// baseline (speedup 1.0000x reference)
#include <cuda_runtime.h>
#include <math.h>

// Problem constants (AGDNConv_14173392077052)
#define NN   50000
#define EE   1600000
#define FIN  256
#define HH   2
#define DD   64
#define KK   3
#define HD   128          // H*D
#define NHH  (NN*HH)

// ---------------- scratch (device globals; no allocation allowed) -----------
__device__ float g_hsrc[NN * HD];          // feat @ W_src            [N,128]
__device__ float g_hdst[NN * HD];          // feat @ W_dst + b        [N,128]
__device__ float g_h[2][NN * HD];          // raw diffusion ping-pong
__device__ float g_hs[KK][NN * HD];        // feat_trans(h_k)         [N,128] x3
__device__ float g_asrc[NN * HH];          // attn logits
__device__ float g_adst[NN * HH];
__device__ float g_sum2[2 * NHH];          // [0,NHH): dst sums, [NHH,2NHH): src sums
__device__ float g_ee[EE * HH];            // exp(leaky(e))
__device__ float g_ae[EE * HH];            // final edge weights a

__device__ __forceinline__ float wsum(float v) {
#pragma unroll
    for (int o = 16; o > 0; o >>= 1) v += __shfl_xor_sync(0xffffffffu, v, o);
    return v;
}

__device__ __forceinline__ float leaky(float x) {
    return x > 0.0f ? x : 0.2f * x;
}

// ---------------- GEMM: C[N,128] = A[N,256] @ B[256,128] (+bias) -----------
// BM=128, BN=64, BK=16, 256 threads, 8x4 micro-tile per thread.
__global__ void gemm_kernel(const float* __restrict__ A,
                            const float* __restrict__ B,
                            const float* __restrict__ bias,
                            int which /*0 -> g_hsrc, 1 -> g_hdst*/) {
    __shared__ float As[16][128];
    __shared__ float Bs[16][64];
    float* C = (which == 0) ? g_hsrc : g_hdst;

    int tid = threadIdx.x;
    int tx = tid & 15;          // 0..15  (col group)
    int ty = tid >> 4;          // 0..15  (row group)
    int m0 = blockIdx.x * 128;
    int n0 = blockIdx.y * 64;

    float acc[8][4];
#pragma unroll
    for (int i = 0; i < 8; i++)
#pragma unroll
        for (int j = 0; j < 4; j++) acc[i][j] = 0.0f;

    int arow  = tid >> 1;        // 0..127
    int acol4 = (tid & 1) * 2;   // 0 or 2
    int brow  = tid >> 4;        // 0..15
    int bcol4 = tid & 15;        // 0..15

    for (int k0 = 0; k0 < FIN; k0 += 16) {
        int gm = m0 + arow;
#pragma unroll
        for (int q = 0; q < 2; q++) {
            float4 v = make_float4(0.f, 0.f, 0.f, 0.f);
            if (gm < NN)
                v = *(const float4*)(A + (size_t)gm * FIN + k0 + (acol4 + q) * 4);
            As[(acol4 + q) * 4 + 0][arow] = v.x;
            As[(acol4 + q) * 4 + 1][arow] = v.y;
            As[(acol4 + q) * 4 + 2][arow] = v.z;
            As[(acol4 + q) * 4 + 3][arow] = v.w;
        }
        float4 bv = *(const float4*)(B + (size_t)(k0 + brow) * HD + n0 + bcol4 * 4);
        *(float4*)(&Bs[brow][bcol4 * 4]) = bv;
        __syncthreads();

#pragma unroll
        for (int kk = 0; kk < 16; kk++) {
            float a[8], b[4];
#pragma unroll
            for (int i = 0; i < 8; i++) a[i] = As[kk][ty * 8 + i];
#pragma unroll
            for (int j = 0; j < 4; j++) b[j] = Bs[kk][tx * 4 + j];
#pragma unroll
            for (int i = 0; i < 8; i++)
#pragma unroll
                for (int j = 0; j < 4; j++) acc[i][j] = fmaf(a[i], b[j], acc[i][j]);
        }
        __syncthreads();
    }

#pragma unroll
    for (int i = 0; i < 8; i++) {
        int gm = m0 + ty * 8 + i;
        if (gm < NN) {
#pragma unroll
            for (int j = 0; j < 4; j++) {
                int gn = n0 + tx * 4 + j;
                float v = acc[i][j];
                if (bias) v += bias[gn];
                C[(size_t)gm * HD + gn] = v;
            }
        }
    }
}

// ---------------- attention projections: a_src/a_dst [N,2] ------------------
// one block (128 thr) per node; 4 warps compute the 4 dots of length 256.
__global__ void attn_kernel(const float* __restrict__ feat,
                            const float* __restrict__ Wa_src,
                            const float* __restrict__ Wa_dst) {
    __shared__ float sf[FIN];
    int n = blockIdx.x;
    int tid = threadIdx.x;
    sf[tid]       = feat[(size_t)n * FIN + tid];
    sf[tid + 128] = feat[(size_t)n * FIN + tid + 128];
    __syncthreads();
    int w = tid >> 5, lane = tid & 31;
    int h = w & 1;
    const float* W = (w < 2) ? Wa_src : Wa_dst;
    float s = 0.0f;
#pragma unroll
    for (int j = 0; j < 8; j++) {
        int k = j * 32 + lane;
        s += sf[k] * W[k * HH + h];
    }
    s = wsum(s);
    if (lane == 0) {
        if (w < 2) g_asrc[n * HH + h] = s;
        else       g_adst[n * HH + h] = s;
    }
}

// ---------------- zero helpers ---------------------------------------------
__global__ void zero_sums_kernel() {
    int i = blockIdx.x * blockDim.x + threadIdx.x;
    if (i < 2 * NHH) g_sum2[i] = 0.0f;
}

__global__ void zero_hop_kernel(int k) {
    int i = blockIdx.x * blockDim.x + threadIdx.x;
    float4* p = (float4*)g_h[k & 1];
    if (i < NN * HD / 4) p[i] = make_float4(0.f, 0.f, 0.f, 0.f);
}

// ---------------- edge softmax pass 1: exp + segment sums -------------------
__global__ void edge_exp_kernel(const int* __restrict__ src,
                                const int* __restrict__ dst) {
    int e = blockIdx.x * blockDim.x + threadIdx.x;
    if (e >= EE) return;
    int s = src[e], d = dst[e];
    float2 as = *(const float2*)(g_asrc + s * HH);
    float2 ad = *(const float2*)(g_adst + d * HH);
    float x0 = expf(leaky(as.x + ad.x));
    float x1 = expf(leaky(as.y + ad.y));
    *(float2*)(g_ee + (size_t)e * HH) = make_float2(x0, x1);
    atomicAdd(&g_sum2[d * HH + 0], x0);
    atomicAdd(&g_sum2[d * HH + 1], x1);
    atomicAdd(&g_sum2[NHH + s * HH + 0], x0);
    atomicAdd(&g_sum2[NHH + s * HH + 1], x1);
}

// ---------------- edge softmax pass 2: a = sqrt(clip*clip) ------------------
__global__ void edge_a_kernel(const int* __restrict__ src,
                              const int* __restrict__ dst) {
    int e = blockIdx.x * blockDim.x + threadIdx.x;
    if (e >= EE) return;
    int s = src[e], d = dst[e];
    float2 ee = *(const float2*)(g_ee + (size_t)e * HH);
    float2 sd = *(const float2*)(g_sum2 + d * HH);
    float2 ss = *(const float2*)(g_sum2 + NHH + s * HH);
    float a0 = sqrtf(fmaxf(ee.x / sd.x, 1e-9f) * fmaxf(ee.x / ss.x, 1e-9f));
    float a1 = sqrtf(fmaxf(ee.y / sd.y, 1e-9f) * fmaxf(ee.y / ss.y, 1e-9f));
    *(float2*)(g_ae + (size_t)e * HH) = make_float2(a0, a1);
}

// ---------------- diffusion hop: warp per edge ------------------------------
// h_out[dst] += a * h_in[src]  (128 floats per edge, float4 per lane)
__global__ void hop_kernel(const int* __restrict__ src,
                           const int* __restrict__ dst,
                           int k) {
    const float* hin = (k == 0) ? g_hsrc : g_h[(k + 1) & 1];
    float* hout = g_h[k & 1];

    int warp = (blockIdx.x * blockDim.x + threadIdx.x) >> 5;
    int lane = threadIdx.x & 31;
    if (warp >= EE) return;
    int s = __ldg(src + warp);
    int d = __ldg(dst + warp);
    float a = __ldg(g_ae + (size_t)warp * HH + (lane >> 4));
    float4 v = __ldg(((const float4*)(hin + (size_t)s * HD)) + lane);
    v.x *= a; v.y *= a; v.z *= a; v.w *= a;
    float* p = hout + (size_t)d * HD + lane * 4;
    asm volatile("red.global.add.v4.f32 [%0], {%1,%2,%3,%4};"
                 :: "l"(p), "f"(v.x), "f"(v.y), "f"(v.z), "f"(v.w)
                 : "memory");
}

// ---------------- feat_trans of hop k output -> g_hs[k] ---------------------
// warp per (n,h); lane holds d = lane, lane+32
__global__ void ftrans_kernel(const float* __restrict__ scale,
                              const float* __restrict__ offset,
                              const float* __restrict__ pemb,
                              int k) {
    const float* hin = g_h[k & 1];
    float* hout = g_hs[k];
    int kidx = k + 1;

    int gw = (blockIdx.x * blockDim.x + threadIdx.x) >> 5;
    int lane = threadIdx.x & 31;
    if (gw >= NHH) return;
    const float* p = hin + (size_t)gw * DD;
    float x0 = p[lane], x1 = p[lane + 32];
    float mean = wsum(x0 + x1) * (1.0f / DD);
    float d0 = x0 - mean, d1 = x1 - mean;
    float var = wsum(d0 * d0 + d1 * d1) * (1.0f / DD) + 1e-9f;
    float r = rsqrtf(var);
    int h = gw & 1;
    int b = kidx * HD + h * DD;
    hout[(size_t)gw * DD + lane]      = d0 * scale[b + lane]      * r + offset[b + lane]      + pemb[b + lane];
    hout[(size_t)gw * DD + lane + 32] = d1 * scale[b + lane + 32] * r + offset[b + lane + 32] + pemb[b + lane + 32];
}

// ---------------- hop attention + residual -> out ---------------------------
__global__ void final_kernel(const float* __restrict__ scale,
                             const float* __restrict__ offset,
                             const float* __restrict__ pemb,
                             const float* __restrict__ attn_l,
                             const float* __restrict__ attn_r,
                             float* __restrict__ out) {
    int gw = (blockIdx.x * blockDim.x + threadIdx.x) >> 5;
    int lane = threadIdx.x & 31;
    if (gw >= NHH) return;
    int h = gw & 1;

    // feat_trans(h_src, 0) -> a_l
    const float* p = g_hsrc + (size_t)gw * DD;
    float x0 = p[lane], x1 = p[lane + 32];
    float mean = wsum(x0 + x1) * (1.0f / DD);
    float d0 = x0 - mean, d1 = x1 - mean;
    float var = wsum(d0 * d0 + d1 * d1) * (1.0f / DD) + 1e-9f;
    float r = rsqrtf(var);
    int b0 = h * DD;  // k=0 base
    float f0 = d0 * scale[b0 + lane]      * r + offset[b0 + lane]      + pemb[b0 + lane];
    float f1 = d1 * scale[b0 + lane + 32] * r + offset[b0 + lane + 32] + pemb[b0 + lane + 32];
    float al = wsum(f0 * attn_l[h * DD + lane] + f1 * attn_l[h * DD + lane + 32]);

    float xs0[KK], xs1[KK], ha[KK];
    float ar0 = attn_r[h * DD + lane], ar1 = attn_r[h * DD + lane + 32];
#pragma unroll
    for (int k = 0; k < KK; k++) {
        xs0[k] = g_hs[k][(size_t)gw * DD + lane];
        xs1[k] = g_hs[k][(size_t)gw * DD + lane + 32];
        ha[k] = leaky(wsum(xs0[k] * ar0 + xs1[k] * ar1) + al);
    }
    float m = fmaxf(ha[0], fmaxf(ha[1], ha[2]));
    float w0 = expf(ha[0] - m), w1 = expf(ha[1] - m), w2 = expf(ha[2] - m);
    float inv = 1.0f / (w0 + w1 + w2);
    w0 *= inv; w1 *= inv; w2 *= inv;

    float o0 = xs0[0] * w0 + xs0[1] * w1 + xs0[2] * w2 + g_hdst[(size_t)gw * DD + lane];
    float o1 = xs1[0] * w0 + xs1[1] * w1 + xs1[2] * w2 + g_hdst[(size_t)gw * DD + lane + 32];
    out[(size_t)gw * DD + lane]      = o0;
    out[(size_t)gw * DD + lane + 32] = o1;
}

// ---------------- launch ----------------------------------------------------
extern "C" void kernel_launch(void* const* d_in, const int* in_sizes, int n_in,
                              void* d_out, int out_size) {
    const float* feat   = (const float*)d_in[0];
    const int*   src    = (const int*)d_in[1];
    const int*   dst    = (const int*)d_in[2];
    const float* W_src  = (const float*)d_in[3];
    const float* W_dst  = (const float*)d_in[4];
    const float* b_dst  = (const float*)d_in[5];
    const float* Wa_src = (const float*)d_in[6];
    const float* Wa_dst = (const float*)d_in[7];
    const float* scale  = (const float*)d_in[8];
    const float* offset = (const float*)d_in[9];
    const float* pemb   = (const float*)d_in[10];
    const float* hal    = (const float*)d_in[11];
    const float* har    = (const float*)d_in[12];
    float* out = (float*)d_out;

    dim3 ggrid((NN + 127) / 128, HD / 64);
    gemm_kernel<<<ggrid, 256>>>(feat, W_src, nullptr, 0);
    gemm_kernel<<<ggrid, 256>>>(feat, W_dst, b_dst, 1);
    attn_kernel<<<NN, 128>>>(feat, Wa_src, Wa_dst);

    zero_sums_kernel<<<(2 * NHH + 255) / 256, 256>>>();
    edge_exp_kernel<<<(EE + 255) / 256, 256>>>(src, dst);
    edge_a_kernel<<<(EE + 255) / 256, 256>>>(src, dst);

    int hop_blocks = (EE * 32 + 255) / 256;      // warp per edge
    int zero_blocks = (NN * HD / 4 + 255) / 256;
    int wg_blocks = (NHH * 32 + 255) / 256;      // warp per (n,h)

    for (int k = 0; k < KK; k++) {
        zero_hop_kernel<<<zero_blocks, 256>>>(k);
        hop_kernel<<<hop_blocks, 256>>>(src, dst, k);
        ftrans_kernel<<<wg_blocks, 256>>>(scale, offset, pemb, k);
    }

    final_kernel<<<wg_blocks, 256>>>(scale, offset, pemb, hal, har, out);
}

// round 2
// speedup vs baseline: 1.5010x; 1.5010x over previous
#include <cuda_runtime.h>
#include <math.h>

// Problem constants (AGDNConv_14173392077052)
#define NN   50000
#define EE   1600000
#define FIN  256
#define HH   2
#define DD   64
#define KK   3
#define HD   128          // H*D
#define NHH  (NN*HH)

// ---------------- scratch (device globals) ----------------------------------
__device__ float g_hsrc[NN * HD];          // feat @ W_src
__device__ float g_hdst[NN * HD];          // feat @ W_dst + b
__device__ float g_h[2][NN * HD];          // raw diffusion ping-pong
__device__ float g_hs[KK][NN * HD];        // feat_trans(h_k)
__device__ float g_asrc[NN * HH];
__device__ float g_adst[NN * HH];
__device__ float g_sum2[2 * NHH];          // [0,NHH): dst sums, [NHH,..): src sums
__device__ float g_ee[EE * HH];            // exp(leaky(e))
// CSR by dst
__device__ int   g_deg[NN];
__device__ int   g_off[NN + 1];
__device__ int   g_cur[NN];
__device__ int   g_csr_src[EE];
__device__ int   g_epos[EE];
__device__ float2 g_csr_a[EE];             // edge weights, CSR order

__device__ __forceinline__ float wsum(float v) {
#pragma unroll
    for (int o = 16; o > 0; o >>= 1) v += __shfl_xor_sync(0xffffffffu, v, o);
    return v;
}
__device__ __forceinline__ float hsum16(float v) {   // reduce within 16-lane half
#pragma unroll
    for (int o = 8; o > 0; o >>= 1) v += __shfl_xor_sync(0xffffffffu, v, o);
    return v;
}
__device__ __forceinline__ float leaky(float x) { return x > 0.0f ? x : 0.2f * x; }

// ---------------- GEMM: C[N,128] = A[N,256] @ B[256,128] (+bias) ------------
__global__ void gemm_kernel(const float* __restrict__ A,
                            const float* __restrict__ B,
                            const float* __restrict__ bias,
                            int which) {
    __shared__ float As[16][128];
    __shared__ float Bs[16][64];
    float* C = (which == 0) ? g_hsrc : g_hdst;

    int tid = threadIdx.x;
    int tx = tid & 15, ty = tid >> 4;
    int m0 = blockIdx.x * 128, n0 = blockIdx.y * 64;

    float acc[8][4];
#pragma unroll
    for (int i = 0; i < 8; i++)
#pragma unroll
        for (int j = 0; j < 4; j++) acc[i][j] = 0.0f;

    int arow = tid >> 1, acol4 = (tid & 1) * 2;
    int brow = tid >> 4, bcol4 = tid & 15;

    for (int k0 = 0; k0 < FIN; k0 += 16) {
        int gm = m0 + arow;
#pragma unroll
        for (int q = 0; q < 2; q++) {
            float4 v = make_float4(0.f, 0.f, 0.f, 0.f);
            if (gm < NN)
                v = *(const float4*)(A + (size_t)gm * FIN + k0 + (acol4 + q) * 4);
            As[(acol4 + q) * 4 + 0][arow] = v.x;
            As[(acol4 + q) * 4 + 1][arow] = v.y;
            As[(acol4 + q) * 4 + 2][arow] = v.z;
            As[(acol4 + q) * 4 + 3][arow] = v.w;
        }
        *(float4*)(&Bs[brow][bcol4 * 4]) =
            *(const float4*)(B + (size_t)(k0 + brow) * HD + n0 + bcol4 * 4);
        __syncthreads();
#pragma unroll
        for (int kk = 0; kk < 16; kk++) {
            float a[8], b[4];
#pragma unroll
            for (int i = 0; i < 8; i++) a[i] = As[kk][ty * 8 + i];
#pragma unroll
            for (int j = 0; j < 4; j++) b[j] = Bs[kk][tx * 4 + j];
#pragma unroll
            for (int i = 0; i < 8; i++)
#pragma unroll
                for (int j = 0; j < 4; j++) acc[i][j] = fmaf(a[i], b[j], acc[i][j]);
        }
        __syncthreads();
    }
#pragma unroll
    for (int i = 0; i < 8; i++) {
        int gm = m0 + ty * 8 + i;
        if (gm < NN) {
#pragma unroll
            for (int j = 0; j < 4; j++) {
                int gn = n0 + tx * 4 + j;
                float v = acc[i][j];
                if (bias) v += bias[gn];
                C[(size_t)gm * HD + gn] = v;
            }
        }
    }
}

// ---------------- attention projections -------------------------------------
__global__ void attn_kernel(const float* __restrict__ feat,
                            const float* __restrict__ Wa_src,
                            const float* __restrict__ Wa_dst) {
    __shared__ float sf[FIN];
    int n = blockIdx.x, tid = threadIdx.x;
    sf[tid]       = feat[(size_t)n * FIN + tid];
    sf[tid + 128] = feat[(size_t)n * FIN + tid + 128];
    __syncthreads();
    int w = tid >> 5, lane = tid & 31, h = w & 1;
    const float* W = (w < 2) ? Wa_src : Wa_dst;
    float s = 0.0f;
#pragma unroll
    for (int j = 0; j < 8; j++) {
        int k = j * 32 + lane;
        s += sf[k] * W[k * HH + h];
    }
    s = wsum(s);
    if (lane == 0) { if (w < 2) g_asrc[n * HH + h] = s; else g_adst[n * HH + h] = s; }
}

// ---------------- zero deg + sums -------------------------------------------
__global__ void zero_misc_kernel() {
    int i = blockIdx.x * blockDim.x + threadIdx.x;
    if (i < NN) g_deg[i] = 0;
    if (i < 2 * NHH) g_sum2[i] = 0.0f;
}

// ---------------- CSR build --------------------------------------------------
__global__ void hist_kernel(const int* __restrict__ dst) {
    int e = blockIdx.x * blockDim.x + threadIdx.x;
    if (e < EE) atomicAdd(&g_deg[dst[e]], 1);
}

__global__ void scan_kernel() {   // 1 block, 1024 threads
    __shared__ int sp[1024];
    const int CH = 49;            // 1024*49 >= NN
    int t = threadIdx.x;
    int lo = t * CH, hi = min(lo + CH, NN);
    int s = 0;
    for (int i = lo; i < hi; i++) s += g_deg[i];
    sp[t] = s;
    __syncthreads();
    for (int o = 1; o < 1024; o <<= 1) {
        int v = (t >= o) ? sp[t - o] : 0;
        __syncthreads();
        sp[t] += v;
        __syncthreads();
    }
    int base = (t == 0) ? 0 : sp[t - 1];
    for (int i = lo; i < hi; i++) {
        g_off[i] = base; g_cur[i] = base; base += g_deg[i];
    }
    if (t == 1023) g_off[NN] = sp[1023];
}

__global__ void scatter_kernel(const int* __restrict__ src,
                               const int* __restrict__ dst) {
    int e = blockIdx.x * blockDim.x + threadIdx.x;
    if (e >= EE) return;
    int pos = atomicAdd(&g_cur[dst[e]], 1);
    g_csr_src[pos] = src[e];
    g_epos[e] = pos;
}

// ---------------- edge softmax pass 1 ----------------------------------------
__global__ void edge_exp_kernel(const int* __restrict__ src,
                                const int* __restrict__ dst) {
    int e = blockIdx.x * blockDim.x + threadIdx.x;
    if (e >= EE) return;
    int s = src[e], d = dst[e];
    float2 as = *(const float2*)(g_asrc + s * HH);
    float2 ad = *(const float2*)(g_adst + d * HH);
    float x0 = expf(leaky(as.x + ad.x));
    float x1 = expf(leaky(as.y + ad.y));
    *(float2*)(g_ee + (size_t)e * HH) = make_float2(x0, x1);
    atomicAdd(&g_sum2[d * HH + 0], x0);
    atomicAdd(&g_sum2[d * HH + 1], x1);
    atomicAdd(&g_sum2[NHH + s * HH + 0], x0);
    atomicAdd(&g_sum2[NHH + s * HH + 1], x1);
}

// ---------------- edge softmax pass 2 -> csr_a -------------------------------
__global__ void edge_a_kernel(const int* __restrict__ src,
                              const int* __restrict__ dst) {
    int e = blockIdx.x * blockDim.x + threadIdx.x;
    if (e >= EE) return;
    int s = src[e], d = dst[e];
    float2 ee = *(const float2*)(g_ee + (size_t)e * HH);
    float2 sd = *(const float2*)(g_sum2 + d * HH);
    float2 ss = *(const float2*)(g_sum2 + NHH + s * HH);
    float a0 = sqrtf(fmaxf(ee.x / sd.x, 1e-9f) * fmaxf(ee.x / ss.x, 1e-9f));
    float a1 = sqrtf(fmaxf(ee.y / sd.y, 1e-9f) * fmaxf(ee.y / ss.y, 1e-9f));
    g_csr_a[g_epos[e]] = make_float2(a0, a1);
}

// ---------------- fused hop: pull-aggregate + feat_trans ---------------------
// warp per dst node: acc[128] in registers (float4/lane), then LN epilogue.
__global__ void hop_agg_kernel(int k,
                               const float* __restrict__ scale,
                               const float* __restrict__ offset,
                               const float* __restrict__ pemb) {
    int node = blockIdx.x * (blockDim.x >> 5) + (threadIdx.x >> 5);
    if (node >= NN) return;
    int lane = threadIdx.x & 31;
    const float* hin = (k == 0) ? g_hsrc : g_h[(k + 1) & 1];

    int beg = g_off[node], end = g_off[node + 1];
    float4 acc = make_float4(0.f, 0.f, 0.f, 0.f);

    for (int j0 = beg; j0 < end; j0 += 32) {
        int cnt = min(32, end - j0);
        int   sj = 0; float2 aj = make_float2(0.f, 0.f);
        if (j0 + lane < end) { sj = g_csr_src[j0 + lane]; aj = g_csr_a[j0 + lane]; }
        for (int t = 0; t < cnt; t++) {
            int   s  = __shfl_sync(0xffffffffu, sj, t);
            float ax = __shfl_sync(0xffffffffu, aj.x, t);
            float ay = __shfl_sync(0xffffffffu, aj.y, t);
            float a = (lane < 16) ? ax : ay;
            float4 v = __ldg(((const float4*)(hin + (size_t)s * HD)) + lane);
            acc.x = fmaf(a, v.x, acc.x);
            acc.y = fmaf(a, v.y, acc.y);
            acc.z = fmaf(a, v.z, acc.z);
            acc.w = fmaf(a, v.w, acc.w);
        }
    }

    // raw h for next hop input
    if (k < KK - 1)
        *(float4*)(g_h[k & 1] + (size_t)node * HD + lane * 4) = acc;

    // feat_trans per head (16 lanes = 64 floats each)
    float sum = hsum16(acc.x + acc.y + acc.z + acc.w);
    float mean = sum * (1.0f / DD);
    float dx = acc.x - mean, dy = acc.y - mean, dz = acc.z - mean, dw = acc.w - mean;
    float ssq = hsum16(dx * dx + dy * dy + dz * dz + dw * dw);
    float r = rsqrtf(ssq * (1.0f / DD) + 1e-9f);
    int h = lane >> 4;
    int base = (k + 1) * HD + h * DD + (lane & 15) * 4;
    float4 o;
    o.x = dx * scale[base + 0] * r + offset[base + 0] + pemb[base + 0];
    o.y = dy * scale[base + 1] * r + offset[base + 1] + pemb[base + 1];
    o.z = dz * scale[base + 2] * r + offset[base + 2] + pemb[base + 2];
    o.w = dw * scale[base + 3] * r + offset[base + 3] + pemb[base + 3];
    *(float4*)(g_hs[k] + (size_t)node * HD + lane * 4) = o;
}

// ---------------- hop attention + residual -> out ----------------------------
__global__ void final_kernel(const float* __restrict__ scale,
                             const float* __restrict__ offset,
                             const float* __restrict__ pemb,
                             const float* __restrict__ attn_l,
                             const float* __restrict__ attn_r,
                             float* __restrict__ out) {
    int gw = (blockIdx.x * blockDim.x + threadIdx.x) >> 5;
    int lane = threadIdx.x & 31;
    if (gw >= NHH) return;
    int h = gw & 1;

    const float* p = g_hsrc + (size_t)gw * DD;
    float x0 = p[lane], x1 = p[lane + 32];
    float mean = wsum(x0 + x1) * (1.0f / DD);
    float d0 = x0 - mean, d1 = x1 - mean;
    float var = wsum(d0 * d0 + d1 * d1) * (1.0f / DD) + 1e-9f;
    float r = rsqrtf(var);
    int b0 = h * DD;
    float f0 = d0 * scale[b0 + lane]      * r + offset[b0 + lane]      + pemb[b0 + lane];
    float f1 = d1 * scale[b0 + lane + 32] * r + offset[b0 + lane + 32] + pemb[b0 + lane + 32];
    float al = wsum(f0 * attn_l[h * DD + lane] + f1 * attn_l[h * DD + lane + 32]);

    float xs0[KK], xs1[KK], ha[KK];
    float ar0 = attn_r[h * DD + lane], ar1 = attn_r[h * DD + lane + 32];
#pragma unroll
    for (int k = 0; k < KK; k++) {
        xs0[k] = g_hs[k][(size_t)gw * DD + lane];
        xs1[k] = g_hs[k][(size_t)gw * DD + lane + 32];
        ha[k] = leaky(wsum(xs0[k] * ar0 + xs1[k] * ar1) + al);
    }
    float m = fmaxf(ha[0], fmaxf(ha[1], ha[2]));
    float w0 = expf(ha[0] - m), w1 = expf(ha[1] - m), w2 = expf(ha[2] - m);
    float inv = 1.0f / (w0 + w1 + w2);
    w0 *= inv; w1 *= inv; w2 *= inv;

    float o0 = xs0[0] * w0 + xs0[1] * w1 + xs0[2] * w2 + g_hdst[(size_t)gw * DD + lane];
    float o1 = xs1[0] * w0 + xs1[1] * w1 + xs1[2] * w2 + g_hdst[(size_t)gw * DD + lane + 32];
    out[(size_t)gw * DD + lane]      = o0;
    out[(size_t)gw * DD + lane + 32] = o1;
}

// ---------------- launch -----------------------------------------------------
extern "C" void kernel_launch(void* const* d_in, const int* in_sizes, int n_in,
                              void* d_out, int out_size) {
    const float* feat   = (const float*)d_in[0];
    const int*   src    = (const int*)d_in[1];
    const int*   dst    = (const int*)d_in[2];
    const float* W_src  = (const float*)d_in[3];
    const float* W_dst  = (const float*)d_in[4];
    const float* b_dst  = (const float*)d_in[5];
    const float* Wa_src = (const float*)d_in[6];
    const float* Wa_dst = (const float*)d_in[7];
    const float* scale  = (const float*)d_in[8];
    const float* offset = (const float*)d_in[9];
    const float* pemb   = (const float*)d_in[10];
    const float* hal    = (const float*)d_in[11];
    const float* har    = (const float*)d_in[12];
    float* out = (float*)d_out;

    zero_misc_kernel<<<(2 * NHH + 255) / 256, 256>>>();

    dim3 ggrid((NN + 127) / 128, HD / 64);
    gemm_kernel<<<ggrid, 256>>>(feat, W_src, nullptr, 0);
    gemm_kernel<<<ggrid, 256>>>(feat, W_dst, b_dst, 1);
    attn_kernel<<<NN, 128>>>(feat, Wa_src, Wa_dst);

    int eb = (EE + 255) / 256;
    hist_kernel<<<eb, 256>>>(dst);
    scan_kernel<<<1, 1024>>>();
    scatter_kernel<<<eb, 256>>>(src, dst);

    edge_exp_kernel<<<eb, 256>>>(src, dst);
    edge_a_kernel<<<eb, 256>>>(src, dst);

    int hop_blocks = (NN * 32 + 255) / 256;   // warp per node
    for (int k = 0; k < KK; k++)
        hop_agg_kernel<<<hop_blocks, 256>>>(k, scale, offset, pemb);

    final_kernel<<<(NHH * 32 + 255) / 256, 256>>>(scale, offset, pemb, hal, har, out);
}

// round 3
// speedup vs baseline: 1.6539x; 1.1019x over previous
#include <cuda_runtime.h>
#include <math.h>

// Problem constants (AGDNConv_14173392077052)
#define NN   50000
#define EE   1600000
#define FIN  256
#define HH   2
#define DD   64
#define KK   3
#define HD   128          // H*D
#define NHH  (NN*HH)

// ---------------- scratch (device globals) ----------------------------------
__device__ float g_hsrc[NN * HD];
__device__ float g_hdst[NN * HD];
__device__ float g_h[2][NN * HD];
__device__ float g_hs[KK][NN * HD];
__device__ float g_asrc[NN * HH];
__device__ float g_adst[NN * HH];
__device__ float g_sum2[2 * NHH];          // [0,NHH): dst sums, [NHH,..): src sums
__device__ float g_ee[EE * HH];            // exp(leaky(e))
// CSR by dst
__device__ int   g_deg[NN];
__device__ int   g_off[NN + 1];
__device__ int   g_cur[NN];
__device__ int   g_csr_src[EE];
__device__ float2 g_csr_a[EE];

__device__ __forceinline__ float wsum(float v) {
#pragma unroll
    for (int o = 16; o > 0; o >>= 1) v += __shfl_xor_sync(0xffffffffu, v, o);
    return v;
}
__device__ __forceinline__ float hsum16(float v) {
#pragma unroll
    for (int o = 8; o > 0; o >>= 1) v += __shfl_xor_sync(0xffffffffu, v, o);
    return v;
}
__device__ __forceinline__ float leaky(float x) { return x > 0.0f ? x : 0.2f * x; }

// ---------------- fused double GEMM: 128x128 tile, 8x8 micro-tile -----------
// y==0: g_hsrc = A @ W_src ; y==1: g_hdst = A @ W_dst + b
__global__ __launch_bounds__(256, 2) void gemm2_kernel(const float* __restrict__ A,
                                                       const float* __restrict__ Wsrc,
                                                       const float* __restrict__ Wdst,
                                                       const float* __restrict__ bias) {
    __shared__ float As[16][128];
    __shared__ float Bs[16][128];
    const float* B = (blockIdx.y == 0) ? Wsrc : Wdst;
    float* C = (blockIdx.y == 0) ? g_hsrc : g_hdst;

    int tid = threadIdx.x;
    int tx = tid & 15, ty = tid >> 4;
    int m0 = blockIdx.x * 128;

    float acc[8][8];
#pragma unroll
    for (int i = 0; i < 8; i++)
#pragma unroll
        for (int j = 0; j < 8; j++) acc[i][j] = 0.0f;

    int arow = tid >> 1, ac8 = (tid & 1) * 8;   // A: 128 rows x 16 k
    int brow = tid >> 4, bc8 = (tid & 15) * 8;  // B: 16 k x 128 n

    for (int k0 = 0; k0 < FIN; k0 += 16) {
        int gm = m0 + arow;
#pragma unroll
        for (int q = 0; q < 2; q++) {
            float4 v = make_float4(0.f, 0.f, 0.f, 0.f);
            if (gm < NN)
                v = *(const float4*)(A + (size_t)gm * FIN + k0 + ac8 + q * 4);
            As[ac8 + q * 4 + 0][arow] = v.x;
            As[ac8 + q * 4 + 1][arow] = v.y;
            As[ac8 + q * 4 + 2][arow] = v.z;
            As[ac8 + q * 4 + 3][arow] = v.w;
        }
#pragma unroll
        for (int q = 0; q < 2; q++)
            *(float4*)(&Bs[brow][bc8 + q * 4]) =
                *(const float4*)(B + (size_t)(k0 + brow) * HD + bc8 + q * 4);
        __syncthreads();
#pragma unroll
        for (int kk = 0; kk < 16; kk++) {
            float a[8], b[8];
#pragma unroll
            for (int i = 0; i < 8; i++) a[i] = As[kk][ty * 8 + i];
#pragma unroll
            for (int j = 0; j < 8; j++) b[j] = Bs[kk][tx * 8 + j];
#pragma unroll
            for (int i = 0; i < 8; i++)
#pragma unroll
                for (int j = 0; j < 8; j++) acc[i][j] = fmaf(a[i], b[j], acc[i][j]);
        }
        __syncthreads();
    }

    bool add_b = (blockIdx.y == 1);
#pragma unroll
    for (int i = 0; i < 8; i++) {
        int gm = m0 + ty * 8 + i;
        if (gm < NN) {
#pragma unroll
            for (int q = 0; q < 2; q++) {
                int gn = tx * 8 + q * 4;
                float4 v = make_float4(acc[i][q * 4], acc[i][q * 4 + 1],
                                       acc[i][q * 4 + 2], acc[i][q * 4 + 3]);
                if (add_b) {
                    float4 bb = *(const float4*)(bias + gn);
                    v.x += bb.x; v.y += bb.y; v.z += bb.z; v.w += bb.w;
                }
                *(float4*)(C + (size_t)gm * HD + gn) = v;
            }
        }
    }
}

// ---------------- attn projections: warp per node, no smem -------------------
__global__ void attn_kernel(const float* __restrict__ feat,
                            const float* __restrict__ Wa_src,
                            const float* __restrict__ Wa_dst) {
    int gw = (blockIdx.x * blockDim.x + threadIdx.x) >> 5;
    int lane = threadIdx.x & 31;
    if (gw >= NN) return;
    float s0 = 0.f, s1 = 0.f, d0 = 0.f, d1 = 0.f;
#pragma unroll
    for (int j = 0; j < 8; j++) {
        int k = j * 32 + lane;
        float f = __ldg(feat + (size_t)gw * FIN + k);
        float2 ws = __ldg((const float2*)(Wa_src + k * HH));
        float2 wd = __ldg((const float2*)(Wa_dst + k * HH));
        s0 = fmaf(f, ws.x, s0); s1 = fmaf(f, ws.y, s1);
        d0 = fmaf(f, wd.x, d0); d1 = fmaf(f, wd.y, d1);
    }
    s0 = wsum(s0); s1 = wsum(s1); d0 = wsum(d0); d1 = wsum(d1);
    if (lane == 0) {
        *(float2*)(g_asrc + gw * HH) = make_float2(s0, s1);
        *(float2*)(g_adst + gw * HH) = make_float2(d0, d1);
    }
}

// ---------------- zero deg + sums -------------------------------------------
__global__ void zero_misc_kernel() {
    int i = blockIdx.x * blockDim.x + threadIdx.x;
    if (i < NN) g_deg[i] = 0;
    if (i < 2 * NHH) g_sum2[i] = 0.0f;
}

// ---------------- edge pass 1: exp + deg histogram + segment sums ------------
__global__ void edge_pass1_kernel(const int* __restrict__ src,
                                  const int* __restrict__ dst) {
    int e = blockIdx.x * blockDim.x + threadIdx.x;
    if (e >= EE) return;
    int s = src[e], d = dst[e];
    float2 as = __ldg((const float2*)(g_asrc + s * HH));
    float2 ad = __ldg((const float2*)(g_adst + d * HH));
    float x0 = expf(leaky(as.x + ad.x));
    float x1 = expf(leaky(as.y + ad.y));
    *(float2*)(g_ee + (size_t)e * HH) = make_float2(x0, x1);
    atomicAdd(&g_deg[d], 1);
    atomicAdd(&g_sum2[d * HH + 0], x0);
    atomicAdd(&g_sum2[d * HH + 1], x1);
    atomicAdd(&g_sum2[NHH + s * HH + 0], x0);
    atomicAdd(&g_sum2[NHH + s * HH + 1], x1);
}

// ---------------- scan (1 block) ---------------------------------------------
__global__ void scan_kernel() {
    __shared__ int sp[1024];
    const int CH = 49;
    int t = threadIdx.x;
    int lo = t * CH, hi = min(lo + CH, NN);
    int s = 0;
    for (int i = lo; i < hi; i++) s += g_deg[i];
    sp[t] = s;
    __syncthreads();
    for (int o = 1; o < 1024; o <<= 1) {
        int v = (t >= o) ? sp[t - o] : 0;
        __syncthreads();
        sp[t] += v;
        __syncthreads();
    }
    int base = (t == 0) ? 0 : sp[t - 1];
    for (int i = lo; i < hi; i++) {
        g_off[i] = base; g_cur[i] = base; base += g_deg[i];
    }
    if (t == 1023) g_off[NN] = sp[1023];
}

// ---------------- edge pass 2: weight + CSR scatter (fused) ------------------
__global__ void edge_pass2_kernel(const int* __restrict__ src,
                                  const int* __restrict__ dst) {
    int e = blockIdx.x * blockDim.x + threadIdx.x;
    if (e >= EE) return;
    int s = src[e], d = dst[e];
    float2 ee = *(const float2*)(g_ee + (size_t)e * HH);
    float2 sd = __ldg((const float2*)(g_sum2 + d * HH));
    float2 ss = __ldg((const float2*)(g_sum2 + NHH + s * HH));
    float a0 = sqrtf(fmaxf(ee.x / sd.x, 1e-9f) * fmaxf(ee.x / ss.x, 1e-9f));
    float a1 = sqrtf(fmaxf(ee.y / sd.y, 1e-9f) * fmaxf(ee.y / ss.y, 1e-9f));
    int pos = atomicAdd(&g_cur[d], 1);
    g_csr_src[pos] = s;
    g_csr_a[pos] = make_float2(a0, a1);
}

// ---------------- fused hop: pull-aggregate (4-way ILP) + feat_trans ---------
__global__ __launch_bounds__(256) void hop_agg_kernel(int k,
                               const float* __restrict__ scale,
                               const float* __restrict__ offset,
                               const float* __restrict__ pemb) {
    int node = blockIdx.x * (blockDim.x >> 5) + (threadIdx.x >> 5);
    if (node >= NN) return;
    int lane = threadIdx.x & 31;
    const float* hin = (k == 0) ? g_hsrc : g_h[(k + 1) & 1];

    int beg = g_off[node], end = g_off[node + 1];
    float4 acc = make_float4(0.f, 0.f, 0.f, 0.f);

    int j = beg;
    for (; j + 4 <= end; j += 4) {
        int s0 = __ldg(g_csr_src + j + 0);
        int s1 = __ldg(g_csr_src + j + 1);
        int s2 = __ldg(g_csr_src + j + 2);
        int s3 = __ldg(g_csr_src + j + 3);
        float2 A0 = __ldg(g_csr_a + j + 0);
        float2 A1 = __ldg(g_csr_a + j + 1);
        float2 A2 = __ldg(g_csr_a + j + 2);
        float2 A3 = __ldg(g_csr_a + j + 3);
        float4 v0 = __ldg(((const float4*)(hin + (size_t)s0 * HD)) + lane);
        float4 v1 = __ldg(((const float4*)(hin + (size_t)s1 * HD)) + lane);
        float4 v2 = __ldg(((const float4*)(hin + (size_t)s2 * HD)) + lane);
        float4 v3 = __ldg(((const float4*)(hin + (size_t)s3 * HD)) + lane);
        float a0 = (lane < 16) ? A0.x : A0.y;
        float a1 = (lane < 16) ? A1.x : A1.y;
        float a2 = (lane < 16) ? A2.x : A2.y;
        float a3 = (lane < 16) ? A3.x : A3.y;
        acc.x = fmaf(a0, v0.x, fmaf(a1, v1.x, fmaf(a2, v2.x, fmaf(a3, v3.x, acc.x))));
        acc.y = fmaf(a0, v0.y, fmaf(a1, v1.y, fmaf(a2, v2.y, fmaf(a3, v3.y, acc.y))));
        acc.z = fmaf(a0, v0.z, fmaf(a1, v1.z, fmaf(a2, v2.z, fmaf(a3, v3.z, acc.z))));
        acc.w = fmaf(a0, v0.w, fmaf(a1, v1.w, fmaf(a2, v2.w, fmaf(a3, v3.w, acc.w))));
    }
    for (; j < end; j++) {
        int s0 = __ldg(g_csr_src + j);
        float2 A0 = __ldg(g_csr_a + j);
        float a0 = (lane < 16) ? A0.x : A0.y;
        float4 v0 = __ldg(((const float4*)(hin + (size_t)s0 * HD)) + lane);
        acc.x = fmaf(a0, v0.x, acc.x);
        acc.y = fmaf(a0, v0.y, acc.y);
        acc.z = fmaf(a0, v0.z, acc.z);
        acc.w = fmaf(a0, v0.w, acc.w);
    }

    if (k < KK - 1)
        *(float4*)(g_h[k & 1] + (size_t)node * HD + lane * 4) = acc;

    // feat_trans per head (16 lanes = 64 floats each)
    float mean = hsum16(acc.x + acc.y + acc.z + acc.w) * (1.0f / DD);
    float dx = acc.x - mean, dy = acc.y - mean, dz = acc.z - mean, dw = acc.w - mean;
    float ssq = hsum16(dx * dx + dy * dy + dz * dz + dw * dw);
    float r = rsqrtf(ssq * (1.0f / DD) + 1e-9f);
    int h = lane >> 4;
    int base = (k + 1) * HD + h * DD + (lane & 15) * 4;
    float4 o;
    o.x = dx * scale[base + 0] * r + offset[base + 0] + pemb[base + 0];
    o.y = dy * scale[base + 1] * r + offset[base + 1] + pemb[base + 1];
    o.z = dz * scale[base + 2] * r + offset[base + 2] + pemb[base + 2];
    o.w = dw * scale[base + 3] * r + offset[base + 3] + pemb[base + 3];
    *(float4*)(g_hs[k] + (size_t)node * HD + lane * 4) = o;
}

// ---------------- hop attention + residual -> out ----------------------------
__global__ void final_kernel(const float* __restrict__ scale,
                             const float* __restrict__ offset,
                             const float* __restrict__ pemb,
                             const float* __restrict__ attn_l,
                             const float* __restrict__ attn_r,
                             float* __restrict__ out) {
    int gw = (blockIdx.x * blockDim.x + threadIdx.x) >> 5;
    int lane = threadIdx.x & 31;
    if (gw >= NHH) return;
    int h = gw & 1;

    const float* p = g_hsrc + (size_t)gw * DD;
    float x0 = p[lane], x1 = p[lane + 32];
    float mean = wsum(x0 + x1) * (1.0f / DD);
    float d0 = x0 - mean, d1 = x1 - mean;
    float var = wsum(d0 * d0 + d1 * d1) * (1.0f / DD) + 1e-9f;
    float r = rsqrtf(var);
    int b0 = h * DD;
    float f0 = d0 * scale[b0 + lane]      * r + offset[b0 + lane]      + pemb[b0 + lane];
    float f1 = d1 * scale[b0 + lane + 32] * r + offset[b0 + lane + 32] + pemb[b0 + lane + 32];
    float al = wsum(f0 * attn_l[h * DD + lane] + f1 * attn_l[h * DD + lane + 32]);

    float xs0[KK], xs1[KK], ha[KK];
    float ar0 = attn_r[h * DD + lane], ar1 = attn_r[h * DD + lane + 32];
#pragma unroll
    for (int k = 0; k < KK; k++) {
        xs0[k] = g_hs[k][(size_t)gw * DD + lane];
        xs1[k] = g_hs[k][(size_t)gw * DD + lane + 32];
        ha[k] = leaky(wsum(xs0[k] * ar0 + xs1[k] * ar1) + al);
    }
    float m = fmaxf(ha[0], fmaxf(ha[1], ha[2]));
    float w0 = expf(ha[0] - m), w1 = expf(ha[1] - m), w2 = expf(ha[2] - m);
    float inv = 1.0f / (w0 + w1 + w2);
    w0 *= inv; w1 *= inv; w2 *= inv;

    float o0 = xs0[0] * w0 + xs0[1] * w1 + xs0[2] * w2 + g_hdst[(size_t)gw * DD + lane];
    float o1 = xs1[0] * w0 + xs1[1] * w1 + xs1[2] * w2 + g_hdst[(size_t)gw * DD + lane + 32];
    out[(size_t)gw * DD + lane]      = o0;
    out[(size_t)gw * DD + lane + 32] = o1;
}

// ---------------- launch -----------------------------------------------------
extern "C" void kernel_launch(void* const* d_in, const int* in_sizes, int n_in,
                              void* d_out, int out_size) {
    const float* feat   = (const float*)d_in[0];
    const int*   src    = (const int*)d_in[1];
    const int*   dst    = (const int*)d_in[2];
    const float* W_src  = (const float*)d_in[3];
    const float* W_dst  = (const float*)d_in[4];
    const float* b_dst  = (const float*)d_in[5];
    const float* Wa_src = (const float*)d_in[6];
    const float* Wa_dst = (const float*)d_in[7];
    const float* scale  = (const float*)d_in[8];
    const float* offset = (const float*)d_in[9];
    const float* pemb   = (const float*)d_in[10];
    const float* hal    = (const float*)d_in[11];
    const float* har    = (const float*)d_in[12];
    float* out = (float*)d_out;

    zero_misc_kernel<<<(2 * NHH + 255) / 256, 256>>>();

    dim3 ggrid((NN + 127) / 128, 2);
    gemm2_kernel<<<ggrid, 256>>>(feat, W_src, W_dst, b_dst);
    attn_kernel<<<(NN * 32 + 255) / 256, 256>>>(feat, Wa_src, Wa_dst);

    int eb = (EE + 255) / 256;
    edge_pass1_kernel<<<eb, 256>>>(src, dst);
    scan_kernel<<<1, 1024>>>();
    edge_pass2_kernel<<<eb, 256>>>(src, dst);

    int hop_blocks = (NN * 32 + 255) / 256;
    for (int k = 0; k < KK; k++)
        hop_agg_kernel<<<hop_blocks, 256>>>(k, scale, offset, pemb);

    final_kernel<<<(NHH * 32 + 255) / 256, 256>>>(scale, offset, pemb, hal, har, out);
}

// round 4
// speedup vs baseline: 1.8848x; 1.1396x over previous
#include <cuda_runtime.h>
#include <math.h>
#include <stdint.h>

// Problem constants (AGDNConv_14173392077052)
#define NN   50000
#define EE   1600000
#define FIN  256
#define HH   2
#define DD   64
#define KK   3
#define HD   128          // H*D
#define NHH  (NN*HH)

// ---------------- scratch (device globals) ----------------------------------
__device__ float g_hsrc[NN * HD];
__device__ float g_hdst[NN * HD];
__device__ float g_h[2][NN * HD];
__device__ float g_hs[KK][NN * HD];
__device__ float g_asrc[NN * HH];
__device__ float g_adst[NN * HH];
__device__ float g_sum2[2 * NHH];          // [0,NHH): dst sums, [NHH,..): src sums
__device__ int   g_deg[NN];
__device__ int   g_off[NN + 1];
__device__ int   g_cur[NN];
__device__ float4 g_csr_ed[EE];            // {src(bits), ee0->a0, ee1->a1, pad}

__device__ __forceinline__ float wsum(float v) {
#pragma unroll
    for (int o = 16; o > 0; o >>= 1) v += __shfl_xor_sync(0xffffffffu, v, o);
    return v;
}
__device__ __forceinline__ float hsum16(float v) {
#pragma unroll
    for (int o = 8; o > 0; o >>= 1) v += __shfl_xor_sync(0xffffffffu, v, o);
    return v;
}
__device__ __forceinline__ float leaky(float x) { return x > 0.0f ? x : 0.2f * x; }

__device__ __forceinline__ uint32_t f2t(float x) {
    uint32_t r; asm("cvt.rna.tf32.f32 %0, %1;" : "=r"(r) : "f"(x)); return r;
}
__device__ __forceinline__ void mma_tf32(float* c, const uint32_t* a, const uint32_t* b) {
    asm volatile("mma.sync.aligned.m16n8k8.row.col.f32.tf32.tf32.f32 "
                 "{%0,%1,%2,%3}, {%4,%5,%6,%7}, {%8,%9}, {%0,%1,%2,%3};"
                 : "+f"(c[0]), "+f"(c[1]), "+f"(c[2]), "+f"(c[3])
                 : "r"(a[0]), "r"(a[1]), "r"(a[2]), "r"(a[3]), "r"(b[0]), "r"(b[1]));
}

// ---------------- tf32 tensor-core GEMM: 128x128 tile, BK=32 ----------------
// blockIdx.y==0: g_hsrc = A @ W_src ; ==1: g_hdst = A @ W_dst + b
#define SA 36
__global__ __launch_bounds__(256, 2) void gemm_tf32_kernel(const float* __restrict__ A,
                                                           const float* __restrict__ Wsrc,
                                                           const float* __restrict__ Wdst,
                                                           const float* __restrict__ bias) {
    __shared__ float As[128][SA];   // [m][k]  (k-minor, pad 36)
    __shared__ float Bs[128][SA];   // [n][k]
    const float* B = (blockIdx.y == 0) ? Wsrc : Wdst;
    float* C = (blockIdx.y == 0) ? g_hsrc : g_hdst;

    int tid = threadIdx.x, lane = tid & 31, wid = tid >> 5;
    int wm0 = (wid >> 2) * 64;   // warp M offset (2 warps over M)
    int wn0 = (wid & 3) * 32;    // warp N offset (4 warps over N)
    int g = lane >> 2, tig = lane & 3;
    int m0 = blockIdx.x * 128;

    float acc[4][4][4];          // [mtile][ntile][frag]
#pragma unroll
    for (int i = 0; i < 4; i++)
#pragma unroll
        for (int j = 0; j < 4; j++)
#pragma unroll
            for (int q = 0; q < 4; q++) acc[i][j][q] = 0.0f;

    for (int k0 = 0; k0 < FIN; k0 += 32) {
        // load A tile: 128 rows x 32 k (float4 along k, no transpose)
#pragma unroll
        for (int it = 0; it < 4; it++) {
            int idx = tid + it * 256;
            int row = idx >> 3, q = idx & 7;
            int gm = m0 + row;
            float4 v = make_float4(0.f, 0.f, 0.f, 0.f);
            if (gm < NN) v = *(const float4*)(A + (size_t)gm * FIN + k0 + q * 4);
            *(float4*)(&As[row][q * 4]) = v;
        }
        // load B tile transposed: B[k][n] -> Bs[n][k]
#pragma unroll
        for (int it = 0; it < 4; it++) {
            int idx = tid + it * 256;
            int kr = idx >> 5, nq = idx & 31;
            float4 v = *(const float4*)(B + (size_t)(k0 + kr) * HD + nq * 4);
            Bs[nq * 4 + 0][kr] = v.x;
            Bs[nq * 4 + 1][kr] = v.y;
            Bs[nq * 4 + 2][kr] = v.z;
            Bs[nq * 4 + 3][kr] = v.w;
        }
        __syncthreads();

#pragma unroll
        for (int kk = 0; kk < 4; kk++) {
            int kb = kk * 8;
            uint32_t af[4][4], bf[4][2];
#pragma unroll
            for (int mt = 0; mt < 4; mt++) {
                int r = wm0 + mt * 16 + g;
                af[mt][0] = f2t(As[r][kb + tig]);
                af[mt][1] = f2t(As[r + 8][kb + tig]);
                af[mt][2] = f2t(As[r][kb + tig + 4]);
                af[mt][3] = f2t(As[r + 8][kb + tig + 4]);
            }
#pragma unroll
            for (int nt = 0; nt < 4; nt++) {
                int c = wn0 + nt * 8 + g;
                bf[nt][0] = f2t(Bs[c][kb + tig]);
                bf[nt][1] = f2t(Bs[c][kb + tig + 4]);
            }
#pragma unroll
            for (int mt = 0; mt < 4; mt++)
#pragma unroll
                for (int nt = 0; nt < 4; nt++)
                    mma_tf32(acc[mt][nt], af[mt], bf[nt]);
        }
        __syncthreads();
    }

    bool add_b = (blockIdx.y == 1);
#pragma unroll
    for (int mt = 0; mt < 4; mt++) {
        int r0 = m0 + wm0 + mt * 16 + g;
        int r1 = r0 + 8;
#pragma unroll
        for (int nt = 0; nt < 4; nt++) {
            int col = wn0 + nt * 8 + tig * 2;
            float2 v0 = make_float2(acc[mt][nt][0], acc[mt][nt][1]);
            float2 v1 = make_float2(acc[mt][nt][2], acc[mt][nt][3]);
            if (add_b) {
                float2 bb = *(const float2*)(bias + col);
                v0.x += bb.x; v0.y += bb.y; v1.x += bb.x; v1.y += bb.y;
            }
            if (r0 < NN) *(float2*)(C + (size_t)r0 * HD + col) = v0;
            if (r1 < NN) *(float2*)(C + (size_t)r1 * HD + col) = v1;
        }
    }
}

// ---------------- attn projections: warp per node ----------------------------
__global__ void attn_kernel(const float* __restrict__ feat,
                            const float* __restrict__ Wa_src,
                            const float* __restrict__ Wa_dst) {
    int gw = (blockIdx.x * blockDim.x + threadIdx.x) >> 5;
    int lane = threadIdx.x & 31;
    if (gw >= NN) return;
    float s0 = 0.f, s1 = 0.f, d0 = 0.f, d1 = 0.f;
#pragma unroll
    for (int j = 0; j < 8; j++) {
        int k = j * 32 + lane;
        float f = __ldg(feat + (size_t)gw * FIN + k);
        float2 ws = __ldg((const float2*)(Wa_src + k * HH));
        float2 wd = __ldg((const float2*)(Wa_dst + k * HH));
        s0 = fmaf(f, ws.x, s0); s1 = fmaf(f, ws.y, s1);
        d0 = fmaf(f, wd.x, d0); d1 = fmaf(f, wd.y, d1);
    }
    s0 = wsum(s0); s1 = wsum(s1); d0 = wsum(d0); d1 = wsum(d1);
    if (lane == 0) {
        *(float2*)(g_asrc + gw * HH) = make_float2(s0, s1);
        *(float2*)(g_adst + gw * HH) = make_float2(d0, d1);
    }
}

// ---------------- zero deg + sums -------------------------------------------
__global__ void zero_misc_kernel() {
    int i = blockIdx.x * blockDim.x + threadIdx.x;
    if (i < NN) g_deg[i] = 0;
    if (i < 2 * NHH) g_sum2[i] = 0.0f;
}

// ---------------- hist: deg histogram (4 edges/thread) -----------------------
__global__ void hist_kernel(const int* __restrict__ dst) {
    int i = blockIdx.x * blockDim.x + threadIdx.x;
    if (i >= EE / 4) return;
    int4 d = __ldg((const int4*)dst + i);
    atomicAdd(&g_deg[d.x], 1);
    atomicAdd(&g_deg[d.y], 1);
    atomicAdd(&g_deg[d.z], 1);
    atomicAdd(&g_deg[d.w], 1);
}

// ---------------- scan (1 block) ---------------------------------------------
__global__ void scan_kernel() {
    __shared__ int sp[1024];
    const int CH = 49;
    int t = threadIdx.x;
    int lo = t * CH, hi = min(lo + CH, NN);
    int s = 0;
    for (int i = lo; i < hi; i++) s += g_deg[i];
    sp[t] = s;
    __syncthreads();
    for (int o = 1; o < 1024; o <<= 1) {
        int v = (t >= o) ? sp[t - o] : 0;
        __syncthreads();
        sp[t] += v;
        __syncthreads();
    }
    int base = (t == 0) ? 0 : sp[t - 1];
    for (int i = lo; i < hi; i++) {
        g_off[i] = base; g_cur[i] = base; base += g_deg[i];
    }
    if (t == 1023) g_off[NN] = sp[1023];
}

// ---------------- pass1: exp + v2 segment sums + CSR scatter -----------------
__global__ void edge_pass1_kernel(const int* __restrict__ src,
                                  const int* __restrict__ dst) {
    int e = blockIdx.x * blockDim.x + threadIdx.x;
    if (e >= EE) return;
    int s = src[e], d = dst[e];
    float2 as = __ldg((const float2*)(g_asrc + s * HH));
    float2 ad = __ldg((const float2*)(g_adst + d * HH));
    float x0 = expf(leaky(as.x + ad.x));
    float x1 = expf(leaky(as.y + ad.y));
    int pos = atomicAdd(&g_cur[d], 1);
    g_csr_ed[pos] = make_float4(__int_as_float(s), x0, x1, 0.f);
    asm volatile("red.global.add.v2.f32 [%0], {%1,%2};"
                 :: "l"(g_sum2 + d * HH), "f"(x0), "f"(x1) : "memory");
    asm volatile("red.global.add.v2.f32 [%0], {%1,%2};"
                 :: "l"(g_sum2 + NHH + s * HH), "f"(x0), "f"(x1) : "memory");
}

// ---------------- pass2: normalize over CSR (warp per node) ------------------
__global__ void edge_norm_kernel() {
    int node = blockIdx.x * (blockDim.x >> 5) + (threadIdx.x >> 5);
    if (node >= NN) return;
    int lane = threadIdx.x & 31;
    float2 sd = *(const float2*)(g_sum2 + node * HH);
    int end = g_off[node + 1];
    for (int j = g_off[node] + lane; j < end; j += 32) {
        float4 r = g_csr_ed[j];
        int s = __float_as_int(r.x);
        float2 ss = __ldg((const float2*)(g_sum2 + NHH + s * HH));
        float a0 = sqrtf(fmaxf(r.y / sd.x, 1e-9f) * fmaxf(r.y / ss.x, 1e-9f));
        float a1 = sqrtf(fmaxf(r.z / sd.y, 1e-9f) * fmaxf(r.z / ss.y, 1e-9f));
        r.y = a0; r.z = a1;
        g_csr_ed[j] = r;
    }
}

// ---------------- fused hop: pull-aggregate (8-way MLP) + feat_trans ---------
__global__ __launch_bounds__(256) void hop_agg_kernel(int k,
                               const float* __restrict__ scale,
                               const float* __restrict__ offset,
                               const float* __restrict__ pemb) {
    int node = blockIdx.x * (blockDim.x >> 5) + (threadIdx.x >> 5);
    if (node >= NN) return;
    int lane = threadIdx.x & 31;
    const float* hin = (k == 0) ? g_hsrc : g_h[(k + 1) & 1];

    int beg = g_off[node], end = g_off[node + 1];
    float4 acc = make_float4(0.f, 0.f, 0.f, 0.f);

    int j = beg;
    for (; j + 8 <= end; j += 8) {
        float4 r[8];
#pragma unroll
        for (int u = 0; u < 8; u++) r[u] = __ldg(g_csr_ed + j + u);
        float4 v[8];
#pragma unroll
        for (int u = 0; u < 8; u++) {
            int s = __float_as_int(r[u].x);
            v[u] = __ldg(((const float4*)(hin + (size_t)s * HD)) + lane);
        }
#pragma unroll
        for (int u = 0; u < 8; u++) {
            float a = (lane < 16) ? r[u].y : r[u].z;
            acc.x = fmaf(a, v[u].x, acc.x);
            acc.y = fmaf(a, v[u].y, acc.y);
            acc.z = fmaf(a, v[u].z, acc.z);
            acc.w = fmaf(a, v[u].w, acc.w);
        }
    }
    for (; j < end; j++) {
        float4 r = __ldg(g_csr_ed + j);
        int s = __float_as_int(r.x);
        float a = (lane < 16) ? r.y : r.z;
        float4 v = __ldg(((const float4*)(hin + (size_t)s * HD)) + lane);
        acc.x = fmaf(a, v.x, acc.x);
        acc.y = fmaf(a, v.y, acc.y);
        acc.z = fmaf(a, v.z, acc.z);
        acc.w = fmaf(a, v.w, acc.w);
    }

    if (k < KK - 1)
        *(float4*)(g_h[k & 1] + (size_t)node * HD + lane * 4) = acc;

    // feat_trans per head (16 lanes = 64 floats each)
    float mean = hsum16(acc.x + acc.y + acc.z + acc.w) * (1.0f / DD);
    float dx = acc.x - mean, dy = acc.y - mean, dz = acc.z - mean, dw = acc.w - mean;
    float ssq = hsum16(dx * dx + dy * dy + dz * dz + dw * dw);
    float r = rsqrtf(ssq * (1.0f / DD) + 1e-9f);
    int h = lane >> 4;
    int base = (k + 1) * HD + h * DD + (lane & 15) * 4;
    float4 o;
    o.x = dx * scale[base + 0] * r + offset[base + 0] + pemb[base + 0];
    o.y = dy * scale[base + 1] * r + offset[base + 1] + pemb[base + 1];
    o.z = dz * scale[base + 2] * r + offset[base + 2] + pemb[base + 2];
    o.w = dw * scale[base + 3] * r + offset[base + 3] + pemb[base + 3];
    *(float4*)(g_hs[k] + (size_t)node * HD + lane * 4) = o;
}

// ---------------- hop attention + residual -> out ----------------------------
__global__ void final_kernel(const float* __restrict__ scale,
                             const float* __restrict__ offset,
                             const float* __restrict__ pemb,
                             const float* __restrict__ attn_l,
                             const float* __restrict__ attn_r,
                             float* __restrict__ out) {
    int gw = (blockIdx.x * blockDim.x + threadIdx.x) >> 5;
    int lane = threadIdx.x & 31;
    if (gw >= NHH) return;
    int h = gw & 1;

    const float* p = g_hsrc + (size_t)gw * DD;
    float x0 = p[lane], x1 = p[lane + 32];
    float mean = wsum(x0 + x1) * (1.0f / DD);
    float d0 = x0 - mean, d1 = x1 - mean;
    float var = wsum(d0 * d0 + d1 * d1) * (1.0f / DD) + 1e-9f;
    float r = rsqrtf(var);
    int b0 = h * DD;
    float f0 = d0 * scale[b0 + lane]      * r + offset[b0 + lane]      + pemb[b0 + lane];
    float f1 = d1 * scale[b0 + lane + 32] * r + offset[b0 + lane + 32] + pemb[b0 + lane + 32];
    float al = wsum(f0 * attn_l[h * DD + lane] + f1 * attn_l[h * DD + lane + 32]);

    float xs0[KK], xs1[KK], ha[KK];
    float ar0 = attn_r[h * DD + lane], ar1 = attn_r[h * DD + lane + 32];
#pragma unroll
    for (int k = 0; k < KK; k++) {
        xs0[k] = g_hs[k][(size_t)gw * DD + lane];
        xs1[k] = g_hs[k][(size_t)gw * DD + lane + 32];
        ha[k] = leaky(wsum(xs0[k] * ar0 + xs1[k] * ar1) + al);
    }
    float m = fmaxf(ha[0], fmaxf(ha[1], ha[2]));
    float w0 = expf(ha[0] - m), w1 = expf(ha[1] - m), w2 = expf(ha[2] - m);
    float inv = 1.0f / (w0 + w1 + w2);
    w0 *= inv; w1 *= inv; w2 *= inv;

    float o0 = xs0[0] * w0 + xs0[1] * w1 + xs0[2] * w2 + g_hdst[(size_t)gw * DD + lane];
    float o1 = xs1[0] * w0 + xs1[1] * w1 + xs1[2] * w2 + g_hdst[(size_t)gw * DD + lane + 32];
    out[(size_t)gw * DD + lane]      = o0;
    out[(size_t)gw * DD + lane + 32] = o1;
}

// ---------------- launch -----------------------------------------------------
extern "C" void kernel_launch(void* const* d_in, const int* in_sizes, int n_in,
                              void* d_out, int out_size) {
    const float* feat   = (const float*)d_in[0];
    const int*   src    = (const int*)d_in[1];
    const int*   dst    = (const int*)d_in[2];
    const float* W_src  = (const float*)d_in[3];
    const float* W_dst  = (const float*)d_in[4];
    const float* b_dst  = (const float*)d_in[5];
    const float* Wa_src = (const float*)d_in[6];
    const float* Wa_dst = (const float*)d_in[7];
    const float* scale  = (const float*)d_in[8];
    const float* offset = (const float*)d_in[9];
    const float* pemb   = (const float*)d_in[10];
    const float* hal    = (const float*)d_in[11];
    const float* har    = (const float*)d_in[12];
    float* out = (float*)d_out;

    zero_misc_kernel<<<(2 * NHH + 255) / 256, 256>>>();

    dim3 ggrid((NN + 127) / 128, 2);
    gemm_tf32_kernel<<<ggrid, 256>>>(feat, W_src, W_dst, b_dst);
    attn_kernel<<<(NN * 32 + 255) / 256, 256>>>(feat, Wa_src, Wa_dst);

    hist_kernel<<<(EE / 4 + 255) / 256, 256>>>(dst);
    scan_kernel<<<1, 1024>>>();
    edge_pass1_kernel<<<(EE + 255) / 256, 256>>>(src, dst);

    int node_blocks = (NN * 32 + 255) / 256;
    edge_norm_kernel<<<node_blocks, 256>>>();

    for (int k = 0; k < KK; k++)
        hop_agg_kernel<<<node_blocks, 256>>>(k, scale, offset, pemb);

    final_kernel<<<(NHH * 32 + 255) / 256, 256>>>(scale, offset, pemb, hal, har, out);
}